// round 2
// baseline (speedup 1.0000x reference)
#include <cuda_runtime.h>
#include <math.h>

// Problem shape (fixed by setup_inputs)
constexpr int   NN = 100000;
constexpr int   FF = 500;
constexpr int   HH = 64;
constexpr int   CC = 40;
constexpr int   EE = 3200000;
constexpr float ALPHA = 0.1f;
constexpr float OMA   = 0.9f;   // 1 - alpha
constexpr int   RV4   = CC / 4; // 10 float4 per row

// ---- scratch (static __device__ arrays; no allocation allowed) ----
__device__ int    g_w64;            // 1 if edge_index is int64, 0 if int32
__device__ int    g_src[EE];
__device__ int    g_dst[EE];
__device__ float  g_enorm[EE];
__device__ float  g_deg[NN];
__device__ float  g_dinv[NN];
__device__ float  g_selfc[NN];
__device__ float  g_h1[(size_t)NN * HH];
__device__ float4 g_h0[(size_t)NN * RV4];
__device__ float4 g_hA[(size_t)NN * RV4];
__device__ float4 g_hB[(size_t)NN * RV4];

// ---------------- dtype sniff ----------------
// edge_index values are uniform in [0, NN). If the buffer is really int32 and
// we read it as u64, the high word is a random node id (>=1 w.p. 1-1e-5), so
// among 64 probes at least one value >= NN with certainty for this input.
__global__ void k_sniff(const unsigned long long* __restrict__ ei) {
    if (threadIdx.x == 0 && blockIdx.x == 0) {
        int ok64 = 1;
        for (int i = 0; i < 64; i++)
            if (ei[i] >= (unsigned long long)NN) { ok64 = 0; break; }
        g_w64 = ok64;
    }
}

__global__ void k_convert(const void* __restrict__ eiv) {
    int e = blockIdx.x * blockDim.x + threadIdx.x;
    if (e >= EE) return;
    if (g_w64) {
        const long long* ei = (const long long*)eiv;
        g_src[e] = (int)ei[e];
        g_dst[e] = (int)ei[(size_t)EE + e];
    } else {
        const int* ei = (const int*)eiv;
        g_src[e] = ei[e];
        g_dst[e] = ei[(size_t)EE + e];
    }
}

__global__ void k_deg_init() {
    int i = blockIdx.x * blockDim.x + threadIdx.x;
    if (i < NN) g_deg[i] = 1.0f;   // self-loop
}

__global__ void k_deg_count() {
    int e = blockIdx.x * blockDim.x + threadIdx.x;
    if (e >= EE) return;
    atomicAdd(&g_deg[g_dst[e]], 1.0f);
}

__global__ void k_dinv() {
    int i = blockIdx.x * blockDim.x + threadIdx.x;
    if (i >= NN) return;
    float d = rsqrtf(g_deg[i]);    // deg >= 1 always
    g_dinv[i] = d;
    g_selfc[i] = OMA * d * d;      // (1-a) * norm of self-loop
}

__global__ void k_enorm() {
    int e = blockIdx.x * blockDim.x + threadIdx.x;
    if (e >= EE) return;
    g_enorm[e] = OMA * g_dinv[g_src[e]] * g_dinv[g_dst[e]];
}

// ---------------- GEMM1: h1 = relu(x @ W1 + b1), [N,500]@[500,64] ----------------
// 64x64 block tile, K-chunk 32, 256 threads, 4x4 micro-tile per thread.
__global__ void k_gemm1(const float* __restrict__ x,
                        const float* __restrict__ W1,
                        const float* __restrict__ b1) {
    __shared__ float As[32][65];  // [k][row]
    __shared__ float Bs[32][64];  // [k][col]
    const int r0  = blockIdx.x * 64;
    const int tid = threadIdx.x;
    const int tx  = tid & 15;       // col group
    const int ty  = tid >> 4;       // row group
    float acc[4][4];
#pragma unroll
    for (int m = 0; m < 4; m++)
#pragma unroll
        for (int n = 0; n < 4; n++) acc[m][n] = 0.0f;

    for (int kb = 0; kb < FF; kb += 32) {
#pragma unroll
        for (int j = 0; j < 8; j++) {           // A: 64 rows x 32 k
            int i   = tid + j * 256;
            int k   = i & 31;
            int row = i >> 5;
            int gr  = r0 + row, gk = kb + k;
            As[k][row] = (gr < NN && gk < FF) ? x[(size_t)gr * FF + gk] : 0.0f;
        }
#pragma unroll
        for (int j = 0; j < 8; j++) {           // B: 32 k x 64 cols
            int i   = tid + j * 256;
            int k   = i >> 6;
            int col = i & 63;
            int gk  = kb + k;
            Bs[k][col] = (gk < FF) ? W1[(size_t)gk * HH + col] : 0.0f;
        }
        __syncthreads();
#pragma unroll
        for (int k = 0; k < 32; k++) {
            float a[4], b[4];
#pragma unroll
            for (int m = 0; m < 4; m++) a[m] = As[k][ty * 4 + m];
#pragma unroll
            for (int n = 0; n < 4; n++) b[n] = Bs[k][tx * 4 + n];
#pragma unroll
            for (int m = 0; m < 4; m++)
#pragma unroll
                for (int n = 0; n < 4; n++) acc[m][n] = fmaf(a[m], b[n], acc[m][n]);
        }
        __syncthreads();
    }
#pragma unroll
    for (int m = 0; m < 4; m++) {
        int row = r0 + ty * 4 + m;
        if (row >= NN) continue;
#pragma unroll
        for (int n = 0; n < 4; n++) {
            int col = tx * 4 + n;
            float v = acc[m][n] + b1[col];
            g_h1[(size_t)row * HH + col] = fmaxf(v, 0.0f);
        }
    }
}

// ---------------- GEMM2: h = h1 @ W2 + b2, [N,64]@[64,40]; writes hA and h0 ----------------
// 32 rows per block, 256 threads: thread = (row r, 5-col group).
__global__ void k_gemm2(const float* __restrict__ W2,
                        const float* __restrict__ b2) {
    __shared__ float W2s[64][40];
    __shared__ float b2s[40];
    __shared__ float h1s[32][64];
    const int tid = threadIdx.x;
    for (int i = tid; i < 64 * 40; i += 256) W2s[i / 40][i % 40] = W2[i];
    if (tid < 40) b2s[tid] = b2[tid];

    const int rb = blockIdx.x * 32;
#pragma unroll
    for (int j = 0; j < 8; j++) {
        int i = tid + j * 256;
        int r = i >> 6, k = i & 63;
        int gr = rb + r;
        h1s[r][k] = (gr < NN) ? g_h1[(size_t)gr * HH + k] : 0.0f;
    }
    __syncthreads();

    const int r  = tid >> 3;        // 0..31
    const int c0 = (tid & 7) * 5;   // 0,5,...,35
    float acc[5];
#pragma unroll
    for (int j = 0; j < 5; j++) acc[j] = b2s[c0 + j];
#pragma unroll
    for (int k = 0; k < 64; k++) {
        float a = h1s[r][k];
#pragma unroll
        for (int j = 0; j < 5; j++) acc[j] = fmaf(a, W2s[k][c0 + j], acc[j]);
    }
    const int row = rb + r;
    if (row < NN) {
        float* hA = (float*)g_hA;
        float* h0 = (float*)g_h0;
#pragma unroll
        for (int j = 0; j < 5; j++) {
            size_t idx = (size_t)row * CC + c0 + j;
            hA[idx] = acc[j];
            h0[idx] = acc[j];
        }
    }
}

// ---------------- propagation ----------------
// h_new = a*h0 + (1-a)*dinv[i]^2*h_cur  (self-loop folded in), then edge scatter adds.
__global__ void k_step_init(int parity) {
    int idx = blockIdx.x * blockDim.x + threadIdx.x;   // float4 index, 10 per row
    if (idx >= NN * RV4) return;
    int row = idx / RV4;
    const float4* cur = parity ? g_hB : g_hA;
    float4*       nw  = parity ? g_hA : g_hB;
    float s = g_selfc[row];
    float4 a = g_h0[idx];
    float4 c = cur[idx];
    nw[idx] = make_float4(fmaf(s, c.x, ALPHA * a.x),
                          fmaf(s, c.y, ALPHA * a.y),
                          fmaf(s, c.z, ALPHA * a.z),
                          fmaf(s, c.w, ALPHA * a.w));
}

__device__ __forceinline__ void red_add_v4(float4* p, float4 v) {
    asm volatile("red.global.add.v4.f32 [%0], {%1,%2,%3,%4};"
                 :: "l"(p), "f"(v.x), "f"(v.y), "f"(v.z), "f"(v.w) : "memory");
}

__global__ void k_scatter(int parity) {
    int e = blockIdx.x * blockDim.x + threadIdx.x;
    if (e >= EE) return;
    const float4* cur = parity ? g_hB : g_hA;
    float4*       nw  = parity ? g_hA : g_hB;
    int   s = g_src[e];
    int   d = g_dst[e];
    float w = g_enorm[e];
    const float4* hs = cur + (size_t)s * RV4;
    float4*       hd = nw  + (size_t)d * RV4;
#pragma unroll
    for (int i = 0; i < RV4; i++) {
        float4 v = hs[i];
        red_add_v4(&hd[i], make_float4(w * v.x, w * v.y, w * v.z, w * v.w));
    }
}

// ---------------- log_softmax over C=40, warp per row ----------------
__global__ void k_logsoftmax(float* __restrict__ out) {
    int warp = threadIdx.x >> 5;
    int lane = threadIdx.x & 31;
    int row  = blockIdx.x * 4 + warp;
    if (row >= NN) return;
    const float* h = (const float*)g_hA + (size_t)row * CC;
    float v0 = (lane < 40) ? h[lane]      : -INFINITY;
    float v1 = (lane < 8)  ? h[32 + lane] : -INFINITY;
    float m = fmaxf(v0, v1);
#pragma unroll
    for (int off = 16; off > 0; off >>= 1)
        m = fmaxf(m, __shfl_xor_sync(0xFFFFFFFFu, m, off));
    float s = ((lane < 40) ? expf(v0 - m) : 0.0f) + ((lane < 8) ? expf(v1 - m) : 0.0f);
#pragma unroll
    for (int off = 16; off > 0; off >>= 1)
        s += __shfl_xor_sync(0xFFFFFFFFu, s, off);
    float ls = logf(s);
    if (lane < 40) out[(size_t)row * CC + lane]      = v0 - m - ls;
    if (lane < 8)  out[(size_t)row * CC + 32 + lane] = v1 - m - ls;
}

// ---------------- launch ----------------
extern "C" void kernel_launch(void* const* d_in, const int* in_sizes, int n_in,
                              void* d_out, int out_size) {
    const float* x  = (const float*)d_in[0];
    const float* W1 = (const float*)d_in[1];
    const float* b1 = (const float*)d_in[2];
    const float* W2 = (const float*)d_in[3];
    const float* b2 = (const float*)d_in[4];
    const void*  ei = d_in[5];
    float* out = (float*)d_out;

    const int TB = 256;
    const int gE = (EE + TB - 1) / TB;     // 12500
    const int gN = (NN + TB - 1) / TB;

    // edge preprocessing
    k_sniff<<<1, 32>>>((const unsigned long long*)ei);
    k_convert<<<gE, TB>>>(ei);
    k_deg_init<<<gN, TB>>>();
    k_deg_count<<<gE, TB>>>();
    k_dinv<<<gN, TB>>>();
    k_enorm<<<gE, TB>>>();

    // MLP
    k_gemm1<<<(NN + 63) / 64, 256>>>(x, W1, b1);
    k_gemm2<<<(NN + 31) / 32, 256>>>(W2, b2);

    // K=10 propagation steps (ping-pong hA/hB; final result lands in hA)
    const int gI = (NN * RV4 + TB - 1) / TB;
    for (int k = 0; k < 10; k++) {
        int parity = k & 1;                 // 0: hA->hB, 1: hB->hA
        k_step_init<<<gI, TB>>>(parity);
        k_scatter<<<gE, TB>>>(parity);
    }

    // output
    k_logsoftmax<<<(NN + 3) / 4, 128>>>(out);
}

// round 3
// speedup vs baseline: 2.8766x; 2.8766x over previous
#include <cuda_runtime.h>
#include <math.h>

// Problem shape (fixed by setup_inputs)
constexpr int   NN = 100000;
constexpr int   FF = 500;
constexpr int   HH = 64;
constexpr int   CC = 40;
constexpr int   EE = 3200000;
constexpr float ALPHA = 0.1f;
constexpr float OMA   = 0.9f;   // 1 - alpha
constexpr int   RV4   = CC / 4; // 10 float4 per row
constexpr int   SCAN_B = (NN + 255) / 256;  // 391 scan blocks

// ---- scratch (static __device__ arrays; no allocation allowed) ----
__device__ int    g_w64;            // 1 if edge_index is int64, 0 if int32
__device__ int    g_degi[NN];       // in-degree (excl self-loop)
__device__ float  g_dinv[NN];
__device__ float  g_selfc[NN];
__device__ int    g_ptr[NN + 1];    // CSR row pointers (by dst)
__device__ int    g_cursor[NN];
__device__ int    g_bsum[SCAN_B];
__device__ int    g_boff[SCAN_B];
__device__ int    g_csr_src[EE];
__device__ float  g_csr_w[EE];
__device__ float  g_h1[(size_t)NN * HH];
__device__ float4 g_h0[(size_t)NN * RV4];
__device__ float4 g_hA[(size_t)NN * RV4];
__device__ float4 g_hB[(size_t)NN * RV4];

// ---------------- dtype sniff ----------------
// edge ids are uniform in [0, NN). Read as u64: if the buffer is int32, the
// high 32 bits of each probe are a random node id (>0 w.p. 1-1e-5), so 64
// probes detect the layout deterministically for this fixed input.
__global__ void k_sniff(const unsigned long long* __restrict__ ei) {
    if (threadIdx.x == 0) {
        int ok64 = 1;
        for (int i = 0; i < 64; i++)
            if (ei[i] >= (unsigned long long)NN) { ok64 = 0; break; }
        g_w64 = ok64;
    }
}

__device__ __forceinline__ int edge_at(const void* eiv, size_t idx) {
    return g_w64 ? (int)((const long long*)eiv)[idx] : ((const int*)eiv)[idx];
}

// ---------------- degree + norm ----------------
__global__ void k_deg_zero() {
    int i = blockIdx.x * blockDim.x + threadIdx.x;
    if (i < NN) g_degi[i] = 0;
}

__global__ void k_deg_count(const void* __restrict__ eiv) {
    int e = blockIdx.x * blockDim.x + threadIdx.x;
    if (e >= EE) return;
    atomicAdd(&g_degi[edge_at(eiv, (size_t)EE + e)], 1);
}

__global__ void k_dinv() {
    int i = blockIdx.x * blockDim.x + threadIdx.x;
    if (i >= NN) return;
    float deg = (float)(g_degi[i] + 1);   // + self-loop
    g_dinv[i]  = rsqrtf(deg);
    g_selfc[i] = OMA / deg;               // (1-a) * dinv^2 (self-loop weight)
}

// ---------------- exclusive scan of degrees -> CSR ptr ----------------
__global__ void k_scan1() {
    __shared__ int sm[256];
    int i = blockIdx.x * 256 + threadIdx.x;
    int v = (i < NN) ? g_degi[i] : 0;
    sm[threadIdx.x] = v;
    __syncthreads();
#pragma unroll
    for (int off = 1; off < 256; off <<= 1) {
        int t = (threadIdx.x >= off) ? sm[threadIdx.x - off] : 0;
        __syncthreads();
        sm[threadIdx.x] += t;
        __syncthreads();
    }
    if (i < NN) g_ptr[i] = sm[threadIdx.x] - v;      // block-local exclusive
    if (threadIdx.x == 255) g_bsum[blockIdx.x] = sm[255];
}

__global__ void k_scan2() {
    __shared__ int sm[512];
    int t = threadIdx.x;
    sm[t] = (t < SCAN_B) ? g_bsum[t] : 0;
    __syncthreads();
#pragma unroll
    for (int off = 1; off < 512; off <<= 1) {
        int v = (t >= off) ? sm[t - off] : 0;
        __syncthreads();
        sm[t] += v;
        __syncthreads();
    }
    if (t < SCAN_B) g_boff[t] = sm[t] - g_bsum[t];   // exclusive
}

__global__ void k_scan3() {
    int i = blockIdx.x * 256 + threadIdx.x;
    if (i < NN) {
        int p = g_ptr[i] + g_boff[blockIdx.x];
        g_ptr[i] = p;
        g_cursor[i] = p;
    }
    if (i == 0) g_ptr[NN] = EE;
}

// ---------------- CSR fill (src + normalized weight) ----------------
__global__ void k_fill(const void* __restrict__ eiv) {
    int e = blockIdx.x * blockDim.x + threadIdx.x;
    if (e >= EE) return;
    int s = edge_at(eiv, e);
    int d = edge_at(eiv, (size_t)EE + e);
    int pos = atomicAdd(&g_cursor[d], 1);
    g_csr_src[pos] = s;
    g_csr_w[pos]   = OMA * g_dinv[s] * g_dinv[d];
}

// ---------------- GEMM1: h1 = relu(x @ W1 + b1), [N,500]@[500,64] ----------------
__global__ void k_gemm1(const float* __restrict__ x,
                        const float* __restrict__ W1,
                        const float* __restrict__ b1) {
    __shared__ float As[32][65];  // [k][row]
    __shared__ float Bs[32][64];  // [k][col]
    const int r0  = blockIdx.x * 64;
    const int tid = threadIdx.x;
    const int tx  = tid & 15;
    const int ty  = tid >> 4;
    float acc[4][4];
#pragma unroll
    for (int m = 0; m < 4; m++)
#pragma unroll
        for (int n = 0; n < 4; n++) acc[m][n] = 0.0f;

    for (int kb = 0; kb < FF; kb += 32) {
#pragma unroll
        for (int j = 0; j < 8; j++) {
            int i   = tid + j * 256;
            int k   = i & 31;
            int row = i >> 5;
            int gr  = r0 + row, gk = kb + k;
            As[k][row] = (gr < NN && gk < FF) ? x[(size_t)gr * FF + gk] : 0.0f;
        }
#pragma unroll
        for (int j = 0; j < 8; j++) {
            int i   = tid + j * 256;
            int k   = i >> 6;
            int col = i & 63;
            int gk  = kb + k;
            Bs[k][col] = (gk < FF) ? W1[(size_t)gk * HH + col] : 0.0f;
        }
        __syncthreads();
#pragma unroll
        for (int k = 0; k < 32; k++) {
            float a[4], b[4];
#pragma unroll
            for (int m = 0; m < 4; m++) a[m] = As[k][ty * 4 + m];
#pragma unroll
            for (int n = 0; n < 4; n++) b[n] = Bs[k][tx * 4 + n];
#pragma unroll
            for (int m = 0; m < 4; m++)
#pragma unroll
                for (int n = 0; n < 4; n++) acc[m][n] = fmaf(a[m], b[n], acc[m][n]);
        }
        __syncthreads();
    }
#pragma unroll
    for (int m = 0; m < 4; m++) {
        int row = r0 + ty * 4 + m;
        if (row >= NN) continue;
#pragma unroll
        for (int n = 0; n < 4; n++) {
            int col = tx * 4 + n;
            float v = acc[m][n] + b1[col];
            g_h1[(size_t)row * HH + col] = fmaxf(v, 0.0f);
        }
    }
}

// ---------------- GEMM2: h = h1 @ W2 + b2 -> hA and h0 ----------------
__global__ void k_gemm2(const float* __restrict__ W2,
                        const float* __restrict__ b2) {
    __shared__ float W2s[64][40];
    __shared__ float b2s[40];
    __shared__ float h1s[32][64];
    const int tid = threadIdx.x;
    for (int i = tid; i < 64 * 40; i += 256) W2s[i / 40][i % 40] = W2[i];
    if (tid < 40) b2s[tid] = b2[tid];

    const int rb = blockIdx.x * 32;
#pragma unroll
    for (int j = 0; j < 8; j++) {
        int i = tid + j * 256;
        int r = i >> 6, k = i & 63;
        int gr = rb + r;
        h1s[r][k] = (gr < NN) ? g_h1[(size_t)gr * HH + k] : 0.0f;
    }
    __syncthreads();

    const int r  = tid >> 3;
    const int c0 = (tid & 7) * 5;
    float acc[5];
#pragma unroll
    for (int j = 0; j < 5; j++) acc[j] = b2s[c0 + j];
#pragma unroll
    for (int k = 0; k < 64; k++) {
        float a = h1s[r][k];
#pragma unroll
        for (int j = 0; j < 5; j++) acc[j] = fmaf(a, W2s[k][c0 + j], acc[j]);
    }
    const int row = rb + r;
    if (row < NN) {
        float* hA = (float*)g_hA;
        float* h0 = (float*)g_h0;
#pragma unroll
        for (int j = 0; j < 5; j++) {
            size_t idx = (size_t)row * CC + c0 + j;
            hA[idx] = acc[j];
            h0[idx] = acc[j];
        }
    }
}

// ---------------- propagation: CSR gather, warp per dst node ----------------
// nw[d] = ALPHA*h0[d] + selfc[d]*cur[d] + sum_e w_e * cur[src_e]
// Lane layout: lane = e_sub*10 + c  (e_sub in 0..2, c = float4 column 0..9);
// lanes 30,31 idle. 3 edges processed per iteration, shfl-reduced at the end.
__global__ void k_prop(int parity) {
    const float4* __restrict__ cur = parity ? g_hB : g_hA;
    float4*       __restrict__ nw  = parity ? g_hA : g_hB;
    int wid  = (blockIdx.x * blockDim.x + threadIdx.x) >> 5;
    if (wid >= NN) return;
    int lane  = threadIdx.x & 31;
    int e_sub = lane / 10;          // 0..3 (3 => idle)
    int c     = lane - e_sub * 10;  // 0..9
    bool act  = lane < 30;

    int beg = g_ptr[wid];
    int end = g_ptr[wid + 1];

    float ax = 0.f, ay = 0.f, az = 0.f, aw = 0.f;
    if (act) {
        for (int e = beg + e_sub; e < end; e += 3) {
            int   s = g_csr_src[e];
            float w = g_csr_w[e];
            float4 v = cur[s * RV4 + c];
            ax = fmaf(w, v.x, ax);
            ay = fmaf(w, v.y, ay);
            az = fmaf(w, v.z, az);
            aw = fmaf(w, v.w, aw);
        }
    }
    // reduce the 3 e_sub groups into lanes 0..9
    const unsigned FULL = 0xFFFFFFFFu;
    float t1, t2;
    t1 = __shfl_down_sync(FULL, ax, 10); t2 = __shfl_down_sync(FULL, ax, 20); ax += t1 + t2;
    t1 = __shfl_down_sync(FULL, ay, 10); t2 = __shfl_down_sync(FULL, ay, 20); ay += t1 + t2;
    t1 = __shfl_down_sync(FULL, az, 10); t2 = __shfl_down_sync(FULL, az, 20); az += t1 + t2;
    t1 = __shfl_down_sync(FULL, aw, 10); t2 = __shfl_down_sync(FULL, aw, 20); aw += t1 + t2;

    if (lane < 10) {
        int   idx = wid * RV4 + lane;
        float sc  = g_selfc[wid];
        float4 h0 = g_h0[idx];
        float4 cc = cur[idx];
        nw[idx] = make_float4(ax + fmaf(sc, cc.x, ALPHA * h0.x),
                              ay + fmaf(sc, cc.y, ALPHA * h0.y),
                              az + fmaf(sc, cc.z, ALPHA * h0.z),
                              aw + fmaf(sc, cc.w, ALPHA * h0.w));
    }
}

// ---------------- log_softmax over C=40, warp per row ----------------
__global__ void k_logsoftmax(float* __restrict__ out) {
    int warp = threadIdx.x >> 5;
    int lane = threadIdx.x & 31;
    int row  = blockIdx.x * 4 + warp;
    if (row >= NN) return;
    const float* h = (const float*)g_hA + (size_t)row * CC;
    float v0 = (lane < 40) ? h[lane]      : -INFINITY;
    float v1 = (lane < 8)  ? h[32 + lane] : -INFINITY;
    float m = fmaxf(v0, v1);
#pragma unroll
    for (int off = 16; off > 0; off >>= 1)
        m = fmaxf(m, __shfl_xor_sync(0xFFFFFFFFu, m, off));
    float s = ((lane < 40) ? expf(v0 - m) : 0.0f) + ((lane < 8) ? expf(v1 - m) : 0.0f);
#pragma unroll
    for (int off = 16; off > 0; off >>= 1)
        s += __shfl_xor_sync(0xFFFFFFFFu, s, off);
    float ls = logf(s);
    if (lane < 40) out[(size_t)row * CC + lane]      = v0 - m - ls;
    if (lane < 8)  out[(size_t)row * CC + 32 + lane] = v1 - m - ls;
}

// ---------------- launch ----------------
extern "C" void kernel_launch(void* const* d_in, const int* in_sizes, int n_in,
                              void* d_out, int out_size) {
    const float* x  = (const float*)d_in[0];
    const float* W1 = (const float*)d_in[1];
    const float* b1 = (const float*)d_in[2];
    const float* W2 = (const float*)d_in[3];
    const float* b2 = (const float*)d_in[4];
    const void*  ei = d_in[5];
    float* out = (float*)d_out;

    const int TB = 256;
    const int gE = (EE + TB - 1) / TB;     // 12500
    const int gN = (NN + TB - 1) / TB;     // 391

    // edge preprocessing -> CSR by dst
    k_sniff<<<1, 32>>>((const unsigned long long*)ei);
    k_deg_zero<<<gN, TB>>>();
    k_deg_count<<<gE, TB>>>(ei);
    k_dinv<<<gN, TB>>>();
    k_scan1<<<SCAN_B, 256>>>();
    k_scan2<<<1, 512>>>();
    k_scan3<<<SCAN_B, 256>>>();
    k_fill<<<gE, TB>>>(ei);

    // MLP
    k_gemm1<<<(NN + 63) / 64, 256>>>(x, W1, b1);
    k_gemm2<<<(NN + 31) / 32, 256>>>(W2, b2);

    // K=10 propagation steps (ping-pong; final lands in hA)
    const int warps_per_block = TB / 32;
    const int gP = (NN + warps_per_block - 1) / warps_per_block;  // 12500
    for (int k = 0; k < 10; k++)
        k_prop<<<gP, TB>>>(k & 1);

    // output
    k_logsoftmax<<<(NN + 3) / 4, 128>>>(out);
}